// round 12
// baseline (speedup 1.0000x reference)
#include <cuda_runtime.h>
#include <cuda_fp16.h>
#include <cstdint>

#define BB 1024   // batch
#define DD 512    // latent dim
#define HH 1024   // MLP hidden
#define TT 64     // time points

// ---------------------------------------------------------------------------
// Persistent device state (no allocs allowed).
// ---------------------------------------------------------------------------
__device__ __align__(16) float g_z  [BB * DD];   // current z (fp32)
__device__ __align__(16) float g_acc[BB * DD];   // k1 + 2k2 + 2k3
__device__ __align__(16) __half g_zin[BB * DD];  // stage input (fp16)
__device__ __align__(16) __half g_h  [BB * HH];  // hidden activation (fp16)
__device__ __align__(16) __half g_W1h[DD * HH];
__device__ __align__(16) __half g_W2h[HH * DD];

// ---------------------------------------------------------------------------
// PTX helpers
// ---------------------------------------------------------------------------
__device__ __forceinline__ void cpa16(void* dst, const void* src) {
    uint32_t d = (uint32_t)__cvta_generic_to_shared(dst);
    asm volatile("cp.async.cg.shared.global [%0], [%1], 16;\n" :: "r"(d), "l"(src));
}
__device__ __forceinline__ void cp_commit() {
    asm volatile("cp.async.commit_group;\n" ::: "memory");
}
template <int N>
__device__ __forceinline__ void cp_wait() {
    asm volatile("cp.async.wait_group %0;\n" :: "n"(N) : "memory");
}
__device__ __forceinline__ void ldsm4(uint32_t* r, const __half* p) {
    uint32_t a = (uint32_t)__cvta_generic_to_shared(p);
    asm volatile("ldmatrix.sync.aligned.m8n8.x4.shared.b16 {%0,%1,%2,%3},[%4];\n"
                 : "=r"(r[0]), "=r"(r[1]), "=r"(r[2]), "=r"(r[3]) : "r"(a));
}
__device__ __forceinline__ void ldsm4t(uint32_t* r, const __half* p) {
    uint32_t a = (uint32_t)__cvta_generic_to_shared(p);
    asm volatile("ldmatrix.sync.aligned.m8n8.x4.trans.shared.b16 {%0,%1,%2,%3},[%4];\n"
                 : "=r"(r[0]), "=r"(r[1]), "=r"(r[2]), "=r"(r[3]) : "r"(a));
}
__device__ __forceinline__ void mma_f16(float* c, const uint32_t* a, uint32_t b0, uint32_t b1) {
    asm volatile("mma.sync.aligned.m16n8k16.row.col.f32.f16.f16.f32 "
                 "{%0,%1,%2,%3}, {%4,%5,%6,%7}, {%8,%9}, {%0,%1,%2,%3};\n"
                 : "+f"(c[0]), "+f"(c[1]), "+f"(c[2]), "+f"(c[3])
                 : "r"(a[0]), "r"(a[1]), "r"(a[2]), "r"(a[3]), "r"(b0), "r"(b1));
}
__device__ __forceinline__ float tanh_fast(float x) {
    float y;
    asm("tanh.approx.f32 %0, %1;\n" : "=f"(y) : "f"(x));
    return y;
}

// ===========================================================================
// GEMM1: h = tanh(zin @ W1 + b1) -> g_h.
// Structural clone of the fast gemm2 config, applied twice per CTA:
//   - CTA block: 128(M) x 64(N), processed as TWO 64x64 subtiles.
//   - Per subtile: KG=4 (BK=128, NT=4), warp tile 32x32 (2m x 2n), 512 thr.
//   - B slab (512k x 64n of W1) resident in smem across both subtiles.
//   - A subtiles stream via 3-buffer cp.async pipeline.
// grid (16 n, 8 m) = 128 CTAs (one wave).
// ---------------------------------------------------------------------------
#define A1STR 136                                   // 128 + 8 halves
#define ABYTE1 (64 * A1STR * 2)                     // 17408 per A buffer
#define B1STR 72
#define SB1_OFF (3 * ABYTE1)                        // 52224
#define SB1_BYTES (512 * B1STR * 2)                 // 73728
#define RED1_OFF (SB1_OFF + SB1_BYTES)              // 125952
#define RSTR1 68
#define RED1_BYTES (4 * 64 * RSTR1 * 4)             // 69632
#define SMEM1 (RED1_OFF + RED1_BYTES)               // 195584
__global__ void __launch_bounds__(512, 1) k_gemm1(const float* __restrict__ b1) {
    extern __shared__ __align__(16) char sm[];
    __half* sB = (__half*)(sm + SB1_OFF);
    const int m0 = blockIdx.y * 128, n0 = blockIdx.x * 64;

    const int tid  = threadIdx.x;
    const int wid  = tid >> 5;
    const int lane = tid & 31;
    const int kg   = wid >> 2;            // 4 k-groups
    const int pos  = wid & 3;
    const int wm = (pos & 1) * 32;
    const int wn = (pos >> 1) * 32;
    const int lr  = lane & 15;
    const int lc8 = (lane >> 4) * 8;

    // ---- Load resident B slab: W1[0:512, n0:n0+64]. 8 chunks/thread. ----
#pragma unroll
    for (int j = 0; j < 8; j++) {
        int cb = tid + j * 512;
        int rb = cb >> 3, nb = (cb & 7) * 8;
        cpa16(sB + rb * B1STR + nb, g_W1h + (size_t)rb * HH + n0 + nb);
    }
    cp_commit();

    // A subtile loader: tile tt = ms*4+it covers rows m0+ms*64..+64,
    // k-cols it*128..+128.  2 chunks/thread.
    auto loadA = [&](int tt, int b) {
        const int ms = tt >> 2, it = tt & 3;
        __half* sA = (__half*)(sm + b * ABYTE1);
        const __half* src = g_zin + (size_t)(m0 + ms * 64) * DD + it * 128;
#pragma unroll
        for (int j = 0; j < 2; j++) {
            int ca = tid + j * 512;
            int r = ca >> 4, cc = (ca & 15) * 8;
            cpa16(sA + r * A1STR + cc, src + (size_t)r * DD + cc);
        }
        cp_commit();
    };

    loadA(0, 0);
    loadA(1, 1);

    float c[2][4][4] = {};
    const int er = lane >> 2, ec = (lane & 3) * 2;

#pragma unroll 1
    for (int ms = 0; ms < 2; ms++) {
#pragma unroll 1
        for (int it = 0; it < 4; it++) {
            const int tt = ms * 4 + it;
            if (tt < 7) cp_wait<1>();
            else        cp_wait<0>();
            __syncthreads();
            if (tt + 2 < 8) loadA(tt + 2, (tt + 2) % 3);

            // compute: exact gemm2 inner loop; B k-row offset = it*128.
            const __half* sA = (const __half*)(sm + (tt % 3) * ABYTE1);
            uint32_t av[2][2][4], bv[2][2][4];
#pragma unroll
            for (int s = 0; s < 2; s++) {
                const int kb = kg * 32 + s * 16;
#pragma unroll
                for (int mt = 0; mt < 2; mt++)
                    ldsm4(av[s][mt], sA + (wm + mt * 16 + lr) * A1STR + kb + lc8);
#pragma unroll
                for (int g = 0; g < 2; g++)
                    ldsm4t(bv[s][g], sB + (it * 128 + kb + lr) * B1STR + wn + g * 16 + lc8);
            }
#pragma unroll
            for (int s = 0; s < 2; s++)
#pragma unroll
                for (int mt = 0; mt < 2; mt++)
#pragma unroll
                    for (int nt = 0; nt < 4; nt++) {
                        const int g = nt >> 1, w = (nt & 1) * 2;
                        mma_f16(c[mt][nt], av[s][mt], bv[s][g][w], bv[s][g][w + 1]);
                    }
        }

        // ---- Subtile epilogue: dump 4 k-group partials, reduce, tanh. ----
        float* red = (float*)(sm + RED1_OFF) + kg * (64 * RSTR1);
#pragma unroll
        for (int mt = 0; mt < 2; mt++)
#pragma unroll
            for (int nt = 0; nt < 4; nt++)
#pragma unroll
                for (int h = 0; h < 2; h++) {
                    int lm = wm + mt * 16 + er + h * 8;
                    int ln = wn + nt * 8 + ec;
                    *reinterpret_cast<float2*>(&red[lm * RSTR1 + ln]) =
                        make_float2(c[mt][nt][2 * h], c[mt][nt][2 * h + 1]);
                }
        __syncthreads();

        const float* rp = (const float*)(sm + RED1_OFF);
        constexpr int RSZ = 64 * RSTR1;
#pragma unroll
        for (int j = 0; j < 4; j++) {
            int p  = tid + j * 512;
            int lm = p >> 5, ln = (p & 31) * 2;
            int off = lm * RSTR1 + ln;
            float2 r0 = *reinterpret_cast<const float2*>(&rp[off]);
            float2 r1 = *reinterpret_cast<const float2*>(&rp[RSZ + off]);
            float2 r2 = *reinterpret_cast<const float2*>(&rp[2 * RSZ + off]);
            float2 r3 = *reinterpret_cast<const float2*>(&rp[3 * RSZ + off]);
            int gn = n0 + ln;
            float2 bv = *reinterpret_cast<const float2*>(&b1[gn]);
            float v0 = tanh_fast(r0.x + r1.x + r2.x + r3.x + bv.x);
            float v1 = tanh_fast(r0.y + r1.y + r2.y + r3.y + bv.y);
            *reinterpret_cast<__half2*>(&g_h[(size_t)(m0 + ms * 64 + lm) * HH + gn]) =
                __halves2half2(__float2half(v0), __float2half(v1));
        }

        // reset accumulators for next subtile
#pragma unroll
        for (int mt = 0; mt < 2; mt++)
#pragma unroll
            for (int nt = 0; nt < 4; nt++)
#pragma unroll
                for (int q = 0; q < 4; q++) c[mt][nt][q] = 0.f;
    }
}

// ===========================================================================
// GEMM2 + RK4 combine (proven config, unchanged): k = h @ W2 + b2.
// Tile 64x64, KG=4 (BK=128, NT=8), 512 thr, grid (8,16)=128, 3-stage.
// ---------------------------------------------------------------------------
#define A2STR 136
#define ABYTE2 (64 * A2STR * 2)                     // 17408
#define BBYTE2 (128 * 72 * 2)                       // 18432
#define BUF2   (ABYTE2 + BBYTE2)                    // 35840
#define SMEM2  (3 * BUF2)                           // 107520
#define RSTR2  68
__global__ void __launch_bounds__(512, 1) k_gemm2(const float* __restrict__ b2,
                                                  const float* __restrict__ t,
                                                  int step, int stage,
                                                  float* __restrict__ traj) {
    extern __shared__ __align__(16) char sm[];
    const int m0 = blockIdx.y * 64, n0 = blockIdx.x * 64;

    const int tid  = threadIdx.x;
    const int wid  = tid >> 5;
    const int lane = tid & 31;
    const int kg   = wid >> 2;            // 4 k-groups
    const int pos  = wid & 3;
    const int wm = (pos & 1) * 32;
    const int wn = (pos >> 1) * 32;
    const int lr  = lane & 15;
    const int lc8 = (lane >> 4) * 8;

    float c[2][4][4] = {};

    auto load_tile = [&](int it, int b) {
        const int kk = it * 128;
        __half* sA = (__half*)(sm + b * BUF2);
        __half* sB = (__half*)(sm + b * BUF2 + ABYTE2);
#pragma unroll
        for (int j = 0; j < 2; j++) {
            int ca = tid + j * 512;                   // A: 64 x 16 chunks
            int r = ca >> 4, cc = (ca & 15) * 8;
            cpa16(sA + r * A2STR + cc, g_h + (size_t)(m0 + r) * HH + kk + cc);
            int cb = tid + j * 512;                   // B: 128 x 8 chunks
            int rb = cb >> 3, nb = (cb & 7) * 8;
            cpa16(sB + rb * 72 + nb, g_W2h + (size_t)(kk + rb) * DD + n0 + nb);
        }
        cp_commit();
    };

    auto compute = [&](int b) {
        const __half* sA = (const __half*)(sm + b * BUF2);
        const __half* sB = (const __half*)(sm + b * BUF2 + ABYTE2);
        uint32_t av[2][2][4], bv[2][2][4];
#pragma unroll
        for (int s = 0; s < 2; s++) {
            const int kb = kg * 32 + s * 16;
#pragma unroll
            for (int mt = 0; mt < 2; mt++)
                ldsm4(av[s][mt], sA + (wm + mt * 16 + lr) * A2STR + kb + lc8);
#pragma unroll
            for (int g = 0; g < 2; g++)
                ldsm4t(bv[s][g], sB + (kb + lr) * 72 + wn + g * 16 + lc8);
        }
#pragma unroll
        for (int s = 0; s < 2; s++)
#pragma unroll
            for (int mt = 0; mt < 2; mt++)
#pragma unroll
                for (int nt = 0; nt < 4; nt++) {
                    const int g = nt >> 1, w = (nt & 1) * 2;
                    mma_f16(c[mt][nt], av[s][mt], bv[s][g][w], bv[s][g][w + 1]);
                }
    };

    load_tile(0, 0);
    load_tile(1, 1);
#pragma unroll 1
    for (int it = 0; it < 8; it++) {
        if (it < 7) cp_wait<1>();
        else        cp_wait<0>();        // last tile: full drain
        __syncthreads();
        if (it + 2 < 8) load_tile(it + 2, (it + 2) % 3);
        compute(it % 3);
    }
    __syncthreads();

    // Reduction dump (4 partials).
    float* red = (float*)sm + kg * (64 * RSTR2);
    const int er = lane >> 2, ec = (lane & 3) * 2;
#pragma unroll
    for (int mt = 0; mt < 2; mt++)
#pragma unroll
        for (int nt = 0; nt < 4; nt++)
#pragma unroll
            for (int h = 0; h < 2; h++) {
                int lm = wm + mt * 16 + er + h * 8;
                int ln = wn + nt * 8 + ec;
                *reinterpret_cast<float2*>(&red[lm * RSTR2 + ln]) =
                    make_float2(c[mt][nt][2 * h], c[mt][nt][2 * h + 1]);
            }
    __syncthreads();

    // Final pass: reduce + bias + RK4 stage update.
    const float* rp = (const float*)sm;
    constexpr int RSZ = 64 * RSTR2;
    const float dt = t[step + 1] - t[step];
#pragma unroll
    for (int j = 0; j < 4; j++) {
        int p  = tid + j * 512;
        int lm = p >> 5, ln = (p & 31) * 2;
        int off = lm * RSTR2 + ln;
        float2 r0 = *reinterpret_cast<const float2*>(&rp[off]);
        float2 r1 = *reinterpret_cast<const float2*>(&rp[RSZ + off]);
        float2 r2 = *reinterpret_cast<const float2*>(&rp[2 * RSZ + off]);
        float2 r3 = *reinterpret_cast<const float2*>(&rp[3 * RSZ + off]);
        int gn = n0 + ln;
        float2 bv = *reinterpret_cast<const float2*>(&b2[gn]);
        float k0 = r0.x + r1.x + r2.x + r3.x + bv.x;
        float k1 = r0.y + r1.y + r2.y + r3.y + bv.y;
        int idx = (m0 + lm) * DD + gn;
        float2 zv = *reinterpret_cast<const float2*>(&g_z[idx]);
        float zi0, zi1;
        if (stage == 0) {
            *reinterpret_cast<float2*>(&g_acc[idx]) = make_float2(k0, k1);
            zi0 = zv.x + 0.5f * dt * k0;
            zi1 = zv.y + 0.5f * dt * k1;
        } else if (stage == 1) {
            float2 a = *reinterpret_cast<const float2*>(&g_acc[idx]);
            *reinterpret_cast<float2*>(&g_acc[idx]) =
                make_float2(a.x + 2.f * k0, a.y + 2.f * k1);
            zi0 = zv.x + 0.5f * dt * k0;
            zi1 = zv.y + 0.5f * dt * k1;
        } else if (stage == 2) {
            float2 a = *reinterpret_cast<const float2*>(&g_acc[idx]);
            *reinterpret_cast<float2*>(&g_acc[idx]) =
                make_float2(a.x + 2.f * k0, a.y + 2.f * k1);
            zi0 = zv.x + dt * k0;
            zi1 = zv.y + dt * k1;
        } else {
            float2 a = *reinterpret_cast<const float2*>(&g_acc[idx]);
            zi0 = zv.x + (dt * (1.0f / 6.0f)) * (a.x + k0);
            zi1 = zv.y + (dt * (1.0f / 6.0f)) * (a.y + k1);
            *reinterpret_cast<float2*>(&g_z[idx]) = make_float2(zi0, zi1);
            *reinterpret_cast<float2*>(&traj[(size_t)(step + 1) * BB * DD + idx]) =
                make_float2(zi0, zi1);
        }
        *reinterpret_cast<__half2*>(&g_zin[idx]) =
            __halves2half2(__float2half(zi0), __float2half(zi1));
    }
}

// ---------------------------------------------------------------------------
// Setup kernels
// ---------------------------------------------------------------------------
__global__ void convert_kernel(const float* __restrict__ src,
                               __half* __restrict__ dst, int n) {
    int i = blockIdx.x * 256 + threadIdx.x;
    if (i < n) dst[i] = __float2half(src[i]);
}

__global__ void init_kernel(const float* __restrict__ z0, float* __restrict__ traj) {
    int i = blockIdx.x * 256 + threadIdx.x;
    if (i < BB * DD) {
        float v = z0[i];
        g_z[i]   = v;
        traj[i]  = v;
        g_zin[i] = __float2half(v);
    }
}

// ---------------------------------------------------------------------------
extern "C" void kernel_launch(void* const* d_in, const int* in_sizes, int n_in,
                              void* d_out, int out_size) {
    const float* z0 = (const float*)d_in[0];
    const float* t  = (const float*)d_in[1];
    const float* W1 = (const float*)d_in[2];
    const float* b1 = (const float*)d_in[3];
    const float* W2 = (const float*)d_in[4];
    const float* b2 = (const float*)d_in[5];
    float* traj = (float*)d_out;

    __half *w1h, *w2h;
    cudaGetSymbolAddress((void**)&w1h, g_W1h);
    cudaGetSymbolAddress((void**)&w2h, g_W2h);

    cudaFuncSetAttribute(k_gemm1, cudaFuncAttributeMaxDynamicSharedMemorySize, SMEM1);
    cudaFuncSetAttribute(k_gemm2, cudaFuncAttributeMaxDynamicSharedMemorySize, SMEM2);

    convert_kernel<<<(DD * HH + 255) / 256, 256>>>(W1, w1h, DD * HH);
    convert_kernel<<<(HH * DD + 255) / 256, 256>>>(W2, w2h, HH * DD);
    init_kernel<<<(BB * DD + 255) / 256, 256>>>(z0, traj);

    dim3 grid1(HH / 64, BB / 128);  // 16 x 8 = 128 CTAs
    dim3 grid2(DD / 64, BB / 64);   // 8 x 16 = 128 CTAs

    for (int step = 0; step < TT - 1; step++) {
        for (int s = 0; s < 4; s++) {
            k_gemm1<<<grid1, 512, SMEM1>>>(b1);
            k_gemm2<<<grid2, 512, SMEM2>>>(b2, t, step, s, traj);
        }
    }
}

// round 13
// speedup vs baseline: 1.0314x; 1.0314x over previous
#include <cuda_runtime.h>
#include <cuda_fp16.h>
#include <cstdint>

#define BB 1024   // batch
#define DD 512    // latent dim
#define HH 1024   // MLP hidden
#define TT 64     // time points

// ---------------------------------------------------------------------------
// Persistent device state (no allocs allowed).
// ---------------------------------------------------------------------------
__device__ __align__(16) float g_z  [BB * DD];   // current z (fp32)
__device__ __align__(16) float g_acc[BB * DD];   // k1 + 2k2 + 2k3
__device__ __align__(16) __half g_zin[BB * DD];  // stage input (fp16)
__device__ __align__(16) __half g_h  [BB * HH];  // hidden activation (fp16)
__device__ __align__(16) __half g_W1h[DD * HH];
__device__ __align__(16) __half g_W2h[HH * DD];
__device__ unsigned g_bar;                        // grid barrier counter

// ---------------------------------------------------------------------------
// SMEM layout (191 KB -> 1 CTA/SM):
//   [0, 73728)            resident W1 slab: 512 x 64 halves, stride 72
//   [73728, 195584)       stream region:
//       phase1: 3 A-buffers (3 x 17408 = 52224) + red at +52224 (69632)
//       phase2: 3 AB-buffers (3 x 35840 = 107520); red overlays base
// ---------------------------------------------------------------------------
#define STREAM_OFF 73728
#define A1STR 136
#define ABYTE1 (64 * A1STR * 2)                  // 17408
#define RED1_OFF (STREAM_OFF + 3 * ABYTE1)       // 125952 (abs)
#define A2STR 136
#define ABYTE2 (64 * A2STR * 2)                  // 17408
#define BBYTE2 (128 * 72 * 2)                    // 18432
#define BUF2   (ABYTE2 + BBYTE2)                 // 35840
#define SMEM_TOTAL 195584

// ---------------------------------------------------------------------------
// PTX helpers
// ---------------------------------------------------------------------------
__device__ __forceinline__ void cpa16(void* dst, const void* src) {
    uint32_t d = (uint32_t)__cvta_generic_to_shared(dst);
    asm volatile("cp.async.cg.shared.global [%0], [%1], 16;\n" :: "r"(d), "l"(src));
}
__device__ __forceinline__ void cp_commit() {
    asm volatile("cp.async.commit_group;\n" ::: "memory");
}
template <int N>
__device__ __forceinline__ void cp_wait() {
    asm volatile("cp.async.wait_group %0;\n" :: "n"(N) : "memory");
}
__device__ __forceinline__ void ldsm4(uint32_t* r, const __half* p) {
    uint32_t a = (uint32_t)__cvta_generic_to_shared(p);
    asm volatile("ldmatrix.sync.aligned.m8n8.x4.shared.b16 {%0,%1,%2,%3},[%4];\n"
                 : "=r"(r[0]), "=r"(r[1]), "=r"(r[2]), "=r"(r[3]) : "r"(a));
}
__device__ __forceinline__ void ldsm4t(uint32_t* r, const __half* p) {
    uint32_t a = (uint32_t)__cvta_generic_to_shared(p);
    asm volatile("ldmatrix.sync.aligned.m8n8.x4.trans.shared.b16 {%0,%1,%2,%3},[%4];\n"
                 : "=r"(r[0]), "=r"(r[1]), "=r"(r[2]), "=r"(r[3]) : "r"(a));
}
__device__ __forceinline__ void mma_f16(float* c, const uint32_t* a, uint32_t b0, uint32_t b1) {
    asm volatile("mma.sync.aligned.m16n8k16.row.col.f32.f16.f16.f32 "
                 "{%0,%1,%2,%3}, {%4,%5,%6,%7}, {%8,%9}, {%0,%1,%2,%3};\n"
                 : "+f"(c[0]), "+f"(c[1]), "+f"(c[2]), "+f"(c[3])
                 : "r"(a[0]), "r"(a[1]), "r"(a[2]), "r"(a[3]), "r"(b0), "r"(b1));
}
__device__ __forceinline__ float tanh_fast(float x) {
    float y;
    asm("tanh.approx.f32 %0, %1;\n" : "=f"(y) : "f"(x));
    return y;
}

// ===========================================================================
// Persistent solver: 128 CTAs x 512 threads, all co-resident (1 CTA/SM).
// Per RK4 stage: phase1 (gemm1 + tanh) -> barrier -> phase2 (gemm2 + RK4).
// ===========================================================================
__global__ void __launch_bounds__(512, 1) k_solver(const float* __restrict__ b1,
                                                   const float* __restrict__ b2,
                                                   const float* __restrict__ t,
                                                   float* __restrict__ traj)
{
    extern __shared__ __align__(16) char sm[];
    __half* sW1 = (__half*)sm;                   // resident slab
    char* stream = sm + STREAM_OFF;

    const int tid  = threadIdx.x;
    const int wid  = tid >> 5;
    const int lane = tid & 31;
    const int kg   = wid >> 2;                   // 4 k-groups
    const int pos  = wid & 3;
    const int wm = (pos & 1) * 32;
    const int wn = (pos >> 1) * 32;
    const int lr  = lane & 15;
    const int lc8 = (lane >> 4) * 8;
    const int er  = lane >> 2, ec = (lane & 3) * 2;

    const int cta = blockIdx.x;                  // 0..127
    const int n1  = (cta & 15) * 64;             // phase1: W1 column block
    const int mg  = cta >> 4;                    // phase1: row groups mg, mg+8
    const int m2  = (cta >> 3) * 64;             // phase2: row block
    const int n2  = (cta & 7) * 64;              // phase2: col block

    // ---- Load resident W1 slab once: W1[0:512, n1:n1+64]. ----
#pragma unroll
    for (int j = 0; j < 8; j++) {
        int cb = tid + j * 512;
        int rb = cb >> 3, nb = (cb & 7) * 8;
        cpa16(sW1 + rb * 72 + nb, g_W1h + (size_t)rb * HH + n1 + nb);
    }
    cp_commit();
    cp_wait<0>();
    __syncthreads();

    unsigned target = 0;

#pragma unroll 1
    for (int ii = 0; ii < (TT - 1) * 4; ii++) {
        const int step = ii >> 2, stage = ii & 3;

        // ================= PHASE 1: h = tanh(zin @ W1 + b1) =================
        auto loadA1 = [&](int tt, int b) {
            const int ms = tt >> 2, it = tt & 3;
            __half* sA = (__half*)(stream + b * ABYTE1);
            const __half* src = g_zin + (size_t)((mg + 8 * ms) * 64) * DD + it * 128;
#pragma unroll
            for (int j = 0; j < 2; j++) {
                int ca = tid + j * 512;
                int r = ca >> 4, cc = (ca & 15) * 8;
                cpa16(sA + r * A1STR + cc, src + (size_t)r * DD + cc);
            }
            cp_commit();
        };
        loadA1(0, 0);
        loadA1(1, 1);
        {
            float c[2][4][4] = {};
#pragma unroll 1
            for (int ms = 0; ms < 2; ms++) {
#pragma unroll 1
                for (int it4 = 0; it4 < 4; it4++) {
                    const int tt = ms * 4 + it4;
                    if (tt < 7) cp_wait<1>();
                    else        cp_wait<0>();
                    __syncthreads();
                    if (tt + 2 < 8) loadA1(tt + 2, (tt + 2) % 3);
                    const __half* sA = (const __half*)(stream + (tt % 3) * ABYTE1);
                    uint32_t av[2][2][4], bv[2][2][4];
#pragma unroll
                    for (int s = 0; s < 2; s++) {
                        const int kb = kg * 32 + s * 16;
#pragma unroll
                        for (int mt = 0; mt < 2; mt++)
                            ldsm4(av[s][mt], sA + (wm + mt * 16 + lr) * A1STR + kb + lc8);
#pragma unroll
                        for (int g = 0; g < 2; g++)
                            ldsm4t(bv[s][g], sW1 + (it4 * 128 + kb + lr) * 72 + wn + g * 16 + lc8);
                    }
#pragma unroll
                    for (int s = 0; s < 2; s++)
#pragma unroll
                        for (int mt = 0; mt < 2; mt++)
#pragma unroll
                            for (int nt = 0; nt < 4; nt++) {
                                const int g = nt >> 1, w = (nt & 1) * 2;
                                mma_f16(c[mt][nt], av[s][mt], bv[s][g][w], bv[s][g][w + 1]);
                            }
                }
                // ---- subtile epilogue: red dump, reduce, tanh, store h ----
                float* red = (float*)(sm + RED1_OFF) + kg * (64 * 68);
#pragma unroll
                for (int mt = 0; mt < 2; mt++)
#pragma unroll
                    for (int nt = 0; nt < 4; nt++)
#pragma unroll
                        for (int h = 0; h < 2; h++) {
                            int lm = wm + mt * 16 + er + h * 8;
                            int ln = wn + nt * 8 + ec;
                            *reinterpret_cast<float2*>(&red[lm * 68 + ln]) =
                                make_float2(c[mt][nt][2 * h], c[mt][nt][2 * h + 1]);
                        }
                __syncthreads();
                const float* rp = (const float*)(sm + RED1_OFF);
                const int mrow = (mg + 8 * ms) * 64;
#pragma unroll
                for (int j = 0; j < 4; j++) {
                    int p  = tid + j * 512;
                    int lm = p >> 5, ln = (p & 31) * 2;
                    int off = lm * 68 + ln;
                    float2 r0 = *reinterpret_cast<const float2*>(&rp[off]);
                    float2 r1 = *reinterpret_cast<const float2*>(&rp[4352 + off]);
                    float2 r2 = *reinterpret_cast<const float2*>(&rp[8704 + off]);
                    float2 r3 = *reinterpret_cast<const float2*>(&rp[13056 + off]);
                    int gn = n1 + ln;
                    float2 bv0 = *reinterpret_cast<const float2*>(&b1[gn]);
                    float v0 = tanh_fast(r0.x + r1.x + r2.x + r3.x + bv0.x);
                    float v1 = tanh_fast(r0.y + r1.y + r2.y + r3.y + bv0.y);
                    *reinterpret_cast<__half2*>(&g_h[(size_t)(mrow + lm) * HH + gn]) =
                        __halves2half2(__float2half(v0), __float2half(v1));
                }
#pragma unroll
                for (int mt = 0; mt < 2; mt++)
#pragma unroll
                    for (int nt = 0; nt < 4; nt++)
#pragma unroll
                        for (int q = 0; q < 4; q++) c[mt][nt][q] = 0.f;
            }
        }

        // ---- grid barrier: g_h visible to all CTAs ----
        __threadfence();
        __syncthreads();
        target += 128;
        if (tid == 0) {
            atomicAdd(&g_bar, 1u);
            while (*((volatile unsigned*)&g_bar) < target) __nanosleep(32);
        }
        __syncthreads();

        // ================= PHASE 2: k = h @ W2 + b2, RK4 update =============
        auto load2 = [&](int it, int b) {
            const int kk = it * 128;
            __half* sA = (__half*)(stream + b * BUF2);
            __half* sB = (__half*)(stream + b * BUF2 + ABYTE2);
#pragma unroll
            for (int j = 0; j < 2; j++) {
                int ca = tid + j * 512;
                int r = ca >> 4, cc = (ca & 15) * 8;
                cpa16(sA + r * A2STR + cc, g_h + (size_t)(m2 + r) * HH + kk + cc);
                int cb = tid + j * 512;
                int rb = cb >> 3, nb = (cb & 7) * 8;
                cpa16(sB + rb * 72 + nb, g_W2h + (size_t)(kk + rb) * DD + n2 + nb);
            }
            cp_commit();
        };
        load2(0, 0);
        load2(1, 1);
        {
            float c[2][4][4] = {};
#pragma unroll 1
            for (int it = 0; it < 8; it++) {
                if (it < 7) cp_wait<1>();
                else        cp_wait<0>();
                __syncthreads();
                if (it + 2 < 8) load2(it + 2, (it + 2) % 3);
                const __half* sA = (const __half*)(stream + (it % 3) * BUF2);
                const __half* sB = (const __half*)(stream + (it % 3) * BUF2 + ABYTE2);
                uint32_t av[2][2][4], bv[2][2][4];
#pragma unroll
                for (int s = 0; s < 2; s++) {
                    const int kb = kg * 32 + s * 16;
#pragma unroll
                    for (int mt = 0; mt < 2; mt++)
                        ldsm4(av[s][mt], sA + (wm + mt * 16 + lr) * A2STR + kb + lc8);
#pragma unroll
                    for (int g = 0; g < 2; g++)
                        ldsm4t(bv[s][g], sB + (kb + lr) * 72 + wn + g * 16 + lc8);
                }
#pragma unroll
                for (int s = 0; s < 2; s++)
#pragma unroll
                    for (int mt = 0; mt < 2; mt++)
#pragma unroll
                        for (int nt = 0; nt < 4; nt++) {
                            const int g = nt >> 1, w = (nt & 1) * 2;
                            mma_f16(c[mt][nt], av[s][mt], bv[s][g][w], bv[s][g][w + 1]);
                        }
            }
            __syncthreads();                    // drain before red overlay

            float* red = (float*)stream + kg * (64 * 68);
#pragma unroll
            for (int mt = 0; mt < 2; mt++)
#pragma unroll
                for (int nt = 0; nt < 4; nt++)
#pragma unroll
                    for (int h = 0; h < 2; h++) {
                        int lm = wm + mt * 16 + er + h * 8;
                        int ln = wn + nt * 8 + ec;
                        *reinterpret_cast<float2*>(&red[lm * 68 + ln]) =
                            make_float2(c[mt][nt][2 * h], c[mt][nt][2 * h + 1]);
                    }
            __syncthreads();

            const float* rp = (const float*)stream;
            const float dt = t[step + 1] - t[step];
#pragma unroll
            for (int j = 0; j < 4; j++) {
                int p  = tid + j * 512;
                int lm = p >> 5, ln = (p & 31) * 2;
                int off = lm * 68 + ln;
                float2 r0 = *reinterpret_cast<const float2*>(&rp[off]);
                float2 r1 = *reinterpret_cast<const float2*>(&rp[4352 + off]);
                float2 r2 = *reinterpret_cast<const float2*>(&rp[8704 + off]);
                float2 r3 = *reinterpret_cast<const float2*>(&rp[13056 + off]);
                int gn = n2 + ln;
                float2 bv0 = *reinterpret_cast<const float2*>(&b2[gn]);
                float k0 = r0.x + r1.x + r2.x + r3.x + bv0.x;
                float k1 = r0.y + r1.y + r2.y + r3.y + bv0.y;
                int idx = (m2 + lm) * DD + gn;
                float2 zv = *reinterpret_cast<const float2*>(&g_z[idx]);
                float zi0, zi1;
                if (stage == 0) {
                    *reinterpret_cast<float2*>(&g_acc[idx]) = make_float2(k0, k1);
                    zi0 = zv.x + 0.5f * dt * k0;
                    zi1 = zv.y + 0.5f * dt * k1;
                } else if (stage == 1) {
                    float2 a = *reinterpret_cast<const float2*>(&g_acc[idx]);
                    *reinterpret_cast<float2*>(&g_acc[idx]) =
                        make_float2(a.x + 2.f * k0, a.y + 2.f * k1);
                    zi0 = zv.x + 0.5f * dt * k0;
                    zi1 = zv.y + 0.5f * dt * k1;
                } else if (stage == 2) {
                    float2 a = *reinterpret_cast<const float2*>(&g_acc[idx]);
                    *reinterpret_cast<float2*>(&g_acc[idx]) =
                        make_float2(a.x + 2.f * k0, a.y + 2.f * k1);
                    zi0 = zv.x + dt * k0;
                    zi1 = zv.y + dt * k1;
                } else {
                    float2 a = *reinterpret_cast<const float2*>(&g_acc[idx]);
                    zi0 = zv.x + (dt * (1.0f / 6.0f)) * (a.x + k0);
                    zi1 = zv.y + (dt * (1.0f / 6.0f)) * (a.y + k1);
                    *reinterpret_cast<float2*>(&g_z[idx]) = make_float2(zi0, zi1);
                    *reinterpret_cast<float2*>(&traj[(size_t)(step + 1) * BB * DD + idx]) =
                        make_float2(zi0, zi1);
                }
                *reinterpret_cast<__half2*>(&g_zin[idx]) =
                    __halves2half2(__float2half(zi0), __float2half(zi1));
            }
        }

        // ---- grid barrier: zin/z/acc visible before next phase1 ----
        __threadfence();
        __syncthreads();
        target += 128;
        if (tid == 0) {
            atomicAdd(&g_bar, 1u);
            while (*((volatile unsigned*)&g_bar) < target) __nanosleep(32);
        }
        __syncthreads();
    }
}

// ---------------------------------------------------------------------------
// Setup kernels
// ---------------------------------------------------------------------------
__global__ void convert_kernel(const float* __restrict__ src,
                               __half* __restrict__ dst, int n) {
    int i = blockIdx.x * 256 + threadIdx.x;
    if (i < n) dst[i] = __float2half(src[i]);
}

__global__ void init_kernel(const float* __restrict__ z0, float* __restrict__ traj) {
    int i = blockIdx.x * 256 + threadIdx.x;
    if (i == 0) g_bar = 0;
    if (i < BB * DD) {
        float v = z0[i];
        g_z[i]   = v;
        traj[i]  = v;
        g_zin[i] = __float2half(v);
    }
}

// ---------------------------------------------------------------------------
extern "C" void kernel_launch(void* const* d_in, const int* in_sizes, int n_in,
                              void* d_out, int out_size) {
    const float* z0 = (const float*)d_in[0];
    const float* t  = (const float*)d_in[1];
    const float* W1 = (const float*)d_in[2];
    const float* b1 = (const float*)d_in[3];
    const float* W2 = (const float*)d_in[4];
    const float* b2 = (const float*)d_in[5];
    float* traj = (float*)d_out;

    __half *w1h, *w2h;
    cudaGetSymbolAddress((void**)&w1h, g_W1h);
    cudaGetSymbolAddress((void**)&w2h, g_W2h);

    cudaFuncSetAttribute(k_solver, cudaFuncAttributeMaxDynamicSharedMemorySize, SMEM_TOTAL);

    convert_kernel<<<(DD * HH + 255) / 256, 256>>>(W1, w1h, DD * HH);
    convert_kernel<<<(HH * DD + 255) / 256, 256>>>(W2, w2h, HH * DD);
    init_kernel<<<(BB * DD + 255) / 256, 256>>>(z0, traj);

    k_solver<<<128, 512, SMEM_TOTAL>>>(b1, b2, t, traj);
}